// round 1
// baseline (speedup 1.0000x reference)
#include <cuda_runtime.h>
#include <cstdint>

#define TT   28      // timesteps
#define IND  28      // input features (layer 0)
#define HID  64      // hidden
#define GG   256     // 4*HID gate rows
#define EE   8       // batch elements per CTA
#define OUTD 10

// Shared memory layout (floats):
//  h1seq [TT][HID][EE]   = 14336
//  xbuf  [IND][EE]       =   224
//  hs    [HID][EE]       =   512
//  act   [EE][GG+8]      =  2112
//  wlin  [OUTD*HID]      =   640
//  blin  [16]            =    16
#define OFF_H1SEQ 0
#define OFF_XBUF  (OFF_H1SEQ + TT*HID*EE)
#define OFF_HS    (OFF_XBUF + IND*EE)
#define OFF_ACT   (OFF_HS + HID*EE)
#define OFF_WLIN  (OFF_ACT + EE*(GG+8))
#define OFF_BLIN  (OFF_WLIN + OUTD*HID)
#define SMEM_FLOATS (OFF_BLIN + 16)
#define SMEM_BYTES (SMEM_FLOATS * 4)

__device__ __forceinline__ float fsig(float x) {
    x = fminf(fmaxf(x, -30.0f), 30.0f);
    return __fdividef(1.0f, 1.0f + __expf(-x));
}
__device__ __forceinline__ float ftanh(float x) {
    x = fminf(fmaxf(x, -15.0f), 15.0f);
    float e = __expf(2.0f * x);
    return __fdividef(e - 1.0f, e + 1.0f);
}

__global__ void __launch_bounds__(256, 1)
rnn_fused_kernel(const float* __restrict__ x,
                 const float* __restrict__ Wih0, const float* __restrict__ Whh0,
                 const float* __restrict__ bih0, const float* __restrict__ bhh0,
                 const float* __restrict__ Wih1, const float* __restrict__ Whh1,
                 const float* __restrict__ bih1, const float* __restrict__ bhh1,
                 const float* __restrict__ Wlin, const float* __restrict__ blin,
                 float* __restrict__ out)
{
    extern __shared__ float sm[];
    float* h1seq = sm + OFF_H1SEQ;
    float* xbuf  = sm + OFF_XBUF;
    float* hs    = sm + OFF_HS;
    float* act   = sm + OFF_ACT;
    float* wlin  = sm + OFF_WLIN;
    float* blin_s= sm + OFF_BLIN;

    const int j  = threadIdx.x;                 // gate row 0..255
    const int e0 = blockIdx.x * EE;             // first batch element

    // zero h state (layer 0)
    hs[j] = 0.0f;
    hs[256 + j] = 0.0f;
    // load linear head weights
    if (j < 128) {
        wlin[j]       = Wlin[j];
        wlin[j + 128] = Wlin[j + 128];
        wlin[j + 256] = Wlin[j + 256];
        wlin[j + 384] = Wlin[j + 384];
        wlin[j + 512] = Wlin[j + 512];
    }
    if (j < OUTD) blin_s[j] = blin[j];

    float c[EE];
#pragma unroll
    for (int e = 0; e < EE; e++) c[e] = 0.0f;

    // ================= Layer 0 =================
    {
        float wi[IND], wh[HID];
#pragma unroll
        for (int k = 0; k < IND; k++) wi[k] = Wih0[j * IND + k];
#pragma unroll
        for (int k = 0; k < HID; k++) wh[k] = Whh0[j * HID + k];
        const float bias = bih0[j] + bhh0[j];

        __syncthreads();

#pragma unroll 1
        for (int t = 0; t < TT; t++) {
            // stage x[:, t, :] into xbuf[k][e]
            if (j < IND * EE) {
                int e = j / IND, k = j % IND;
                xbuf[k * EE + e] = x[(size_t)(e0 + e) * (TT * IND) + t * IND + k];
            }
            __syncthreads();

            float acc[EE];
#pragma unroll
            for (int e = 0; e < EE; e++) acc[e] = bias;

#pragma unroll
            for (int k = 0; k < IND; k++) {
                float w = wi[k];
                float4 a = *reinterpret_cast<const float4*>(&xbuf[k * EE]);
                float4 b = *reinterpret_cast<const float4*>(&xbuf[k * EE + 4]);
                acc[0] += a.x * w; acc[1] += a.y * w; acc[2] += a.z * w; acc[3] += a.w * w;
                acc[4] += b.x * w; acc[5] += b.y * w; acc[6] += b.z * w; acc[7] += b.w * w;
            }
#pragma unroll
            for (int k = 0; k < HID; k++) {
                float w = wh[k];
                float4 a = *reinterpret_cast<const float4*>(&hs[k * EE]);
                float4 b = *reinterpret_cast<const float4*>(&hs[k * EE + 4]);
                acc[0] += a.x * w; acc[1] += a.y * w; acc[2] += a.z * w; acc[3] += a.w * w;
                acc[4] += b.x * w; acc[5] += b.y * w; acc[6] += b.z * w; acc[7] += b.w * w;
            }

            const int gt = j >> 6;   // 0:i 1:f 2:g 3:o
#pragma unroll
            for (int e = 0; e < EE; e++) {
                float v = (gt == 2) ? ftanh(acc[e]) : fsig(acc[e]);
                act[e * (GG + 8) + j] = v;
            }
            __syncthreads();

            if (j < HID) {
#pragma unroll
                for (int e = 0; e < EE; e++) {
                    const float* ae = &act[e * (GG + 8)];
                    float ig = ae[j];
                    float fg = ae[HID + j];
                    float gg = ae[2 * HID + j];
                    float og = ae[3 * HID + j];
                    c[e] = fg * c[e] + ig * gg;
                    float h = og * ftanh(c[e]);
                    hs[j * EE + e] = h;
                    h1seq[(t * HID + j) * EE + e] = h;
                }
            }
            __syncthreads();
        }
    }

    // reset state for layer 1
#pragma unroll
    for (int e = 0; e < EE; e++) c[e] = 0.0f;
    hs[j] = 0.0f;
    hs[256 + j] = 0.0f;

    // ================= Layer 1 =================
    {
        float wi[HID], wh[HID];
#pragma unroll
        for (int k = 0; k < HID; k++) wi[k] = Wih1[j * HID + k];
#pragma unroll
        for (int k = 0; k < HID; k++) wh[k] = Whh1[j * HID + k];
        const float bias = bih1[j] + bhh1[j];

        __syncthreads();

#pragma unroll 1
        for (int t = 0; t < TT; t++) {
            const float* h1t = &h1seq[t * HID * EE];

            float acc[EE];
#pragma unroll
            for (int e = 0; e < EE; e++) acc[e] = bias;

#pragma unroll
            for (int k = 0; k < HID; k++) {
                float wa = wi[k];
                float wb = wh[k];
                float4 p = *reinterpret_cast<const float4*>(&h1t[k * EE]);
                float4 q = *reinterpret_cast<const float4*>(&h1t[k * EE + 4]);
                float4 r = *reinterpret_cast<const float4*>(&hs[k * EE]);
                float4 s = *reinterpret_cast<const float4*>(&hs[k * EE + 4]);
                acc[0] += p.x * wa; acc[1] += p.y * wa; acc[2] += p.z * wa; acc[3] += p.w * wa;
                acc[4] += q.x * wa; acc[5] += q.y * wa; acc[6] += q.z * wa; acc[7] += q.w * wa;
                acc[0] += r.x * wb; acc[1] += r.y * wb; acc[2] += r.z * wb; acc[3] += r.w * wb;
                acc[4] += s.x * wb; acc[5] += s.y * wb; acc[6] += s.z * wb; acc[7] += s.w * wb;
            }

            const int gt = j >> 6;
#pragma unroll
            for (int e = 0; e < EE; e++) {
                float v = (gt == 2) ? ftanh(acc[e]) : fsig(acc[e]);
                act[e * (GG + 8) + j] = v;
            }
            __syncthreads();

            if (j < HID) {
#pragma unroll
                for (int e = 0; e < EE; e++) {
                    const float* ae = &act[e * (GG + 8)];
                    float ig = ae[j];
                    float fg = ae[HID + j];
                    float gg = ae[2 * HID + j];
                    float og = ae[3 * HID + j];
                    c[e] = fg * c[e] + ig * gg;
                    float h = og * ftanh(c[e]);
                    hs[j * EE + e] = h;
                }
            }
            __syncthreads();
        }
    }

    // ================= Linear head =================
    // hs now holds h2[T-1] as [k][e]
    if (j < OUTD * EE) {
        int e = j & (EE - 1);
        int o = j >> 3;
        float s = blin_s[o];
#pragma unroll
        for (int k = 0; k < HID; k++)
            s += wlin[o * HID + k] * hs[k * EE + e];
        out[(size_t)(e0 + e) * OUTD + o] = s;
    }
}

extern "C" void kernel_launch(void* const* d_in, const int* in_sizes, int n_in,
                              void* d_out, int out_size)
{
    const float* x    = (const float*)d_in[0];
    const float* Wih0 = (const float*)d_in[1];
    const float* Whh0 = (const float*)d_in[2];
    const float* bih0 = (const float*)d_in[3];
    const float* bhh0 = (const float*)d_in[4];
    const float* Wih1 = (const float*)d_in[5];
    const float* Whh1 = (const float*)d_in[6];
    const float* bih1 = (const float*)d_in[7];
    const float* bhh1 = (const float*)d_in[8];
    const float* Wlin = (const float*)d_in[9];
    const float* blin = (const float*)d_in[10];
    float* out = (float*)d_out;

    int B = in_sizes[0] / (TT * IND);   // 16384
    int grid = B / EE;                  // 2048

    cudaFuncSetAttribute(rnn_fused_kernel,
                         cudaFuncAttributeMaxDynamicSharedMemorySize, SMEM_BYTES);
    rnn_fused_kernel<<<grid, 256, SMEM_BYTES>>>(
        x, Wih0, Whh0, bih0, bhh0, Wih1, Whh1, bih1, bhh1, Wlin, blin, out);
}

// round 2
// speedup vs baseline: 1.3445x; 1.3445x over previous
#include <cuda_runtime.h>
#include <cstdint>

#define TT   28      // timesteps
#define IND  28      // input features (layer 0)
#define HID  64      // hidden
#define GG   256     // 4*HID gate rows
#define EE   16      // batch elements per CTA
#define ES   20      // padded row stride for hs/h1seq (16 data + 4 pad), 80B = 16B-aligned rows
#define AS   (GG+8)  // act row stride
#define OUTD 10

// Shared memory layout (floats), all offsets 16B aligned:
//  h1seq [TT][HID][ES]  = 35840
//  xbuf  [2][IND][EE]   =   896
//  hs    [HID][ES]      =  1280
//  act   [EE][AS]       =  4224
//  wlin  [OUTD*HID]     =   640
//  blin  [16]           =    16
#define OFF_H1SEQ 0
#define OFF_XBUF  (OFF_H1SEQ + TT*HID*ES)
#define OFF_HS    (OFF_XBUF + 2*IND*EE)
#define OFF_ACT   (OFF_HS + HID*ES)
#define OFF_WLIN  (OFF_ACT + EE*AS)
#define OFF_BLIN  (OFF_WLIN + OUTD*HID)
#define SMEM_FLOATS (OFF_BLIN + 16)
#define SMEM_BYTES  (SMEM_FLOATS * 4)

typedef unsigned long long u64;

__device__ __forceinline__ u64 splat2(float w) {
    u64 r; asm("mov.b64 %0, {%1, %1};" : "=l"(r) : "f"(w)); return r;
}
__device__ __forceinline__ void ffma2(u64& d, u64 a, u64 b) {
    asm("fma.rn.f32x2 %0, %1, %2, %0;" : "+l"(d) : "l"(a), "l"(b));
}
__device__ __forceinline__ float2 unpack2(u64 v) {
    float2 f; asm("mov.b64 {%0, %1}, %2;" : "=f"(f.x), "=f"(f.y) : "l"(v)); return f;
}

__device__ __forceinline__ float fsig(float x) {
    x = fminf(fmaxf(x, -30.0f), 30.0f);
    return __fdividef(1.0f, 1.0f + __expf(-x));
}
__device__ __forceinline__ float ftanh(float x) {
    x = fminf(fmaxf(x, -15.0f), 15.0f);
    float e = __expf(2.0f * x);
    return __fdividef(e - 1.0f, e + 1.0f);
}

// accumulate 16 batch elements (8 f32x2 pairs) from a 16-float row at `ptr`
#define GACC(accs, ptr, pw) do {                                             \
    const ulonglong2* _p = reinterpret_cast<const ulonglong2*>(ptr);         \
    ulonglong2 _q0 = _p[0], _q1 = _p[1], _q2 = _p[2], _q3 = _p[3];           \
    ffma2((accs)[0], _q0.x, (pw)); ffma2((accs)[1], _q0.y, (pw));            \
    ffma2((accs)[2], _q1.x, (pw)); ffma2((accs)[3], _q1.y, (pw));            \
    ffma2((accs)[4], _q2.x, (pw)); ffma2((accs)[5], _q2.y, (pw));            \
    ffma2((accs)[6], _q3.x, (pw)); ffma2((accs)[7], _q3.y, (pw));            \
} while (0)

__global__ void __launch_bounds__(256, 1)
rnn_fused_kernel(const float* __restrict__ x,
                 const float* __restrict__ Wih0, const float* __restrict__ Whh0,
                 const float* __restrict__ bih0, const float* __restrict__ bhh0,
                 const float* __restrict__ Wih1, const float* __restrict__ Whh1,
                 const float* __restrict__ bih1, const float* __restrict__ bhh1,
                 const float* __restrict__ Wlin, const float* __restrict__ blin,
                 float* __restrict__ out)
{
    extern __shared__ float sm[];
    float* h1seq = sm + OFF_H1SEQ;
    float* xbuf  = sm + OFF_XBUF;
    float* hs    = sm + OFF_HS;
    float* act   = sm + OFF_ACT;
    float* wlin  = sm + OFF_WLIN;
    float* blin_s= sm + OFF_BLIN;

    const int j  = threadIdx.x;             // gate row 0..255
    const int e0 = blockIdx.x * EE;
    const int unit = j & 63;
    const int eb   = (j >> 6) << 2;         // 4 batch elems per thread in update
    const int gt   = j >> 6;                // gate type: 0:i 1:f 2:g 3:o

    // init: zero hs, stage xbuf[0], load linear head
    for (int idx = j; idx < HID * ES; idx += 256) hs[idx] = 0.0f;
    for (int idx = j; idx < IND * EE; idx += 256) {
        int e = idx & (EE - 1), k = idx >> 4;
        xbuf[k * EE + e] = x[(size_t)(e0 + e) * (TT * IND) + 0 * IND + k];
    }
    for (int idx = j; idx < OUTD * HID; idx += 256) wlin[idx] = Wlin[idx];
    if (j < OUTD) blin_s[j] = blin[j];

    float c[4];
#pragma unroll
    for (int q = 0; q < 4; q++) c[q] = 0.0f;

    // ================= Layer 0 =================
    {
        float wi[IND], wh[HID];
#pragma unroll
        for (int k = 0; k < IND; k++) wi[k] = Wih0[j * IND + k];
#pragma unroll
        for (int k = 0; k < HID; k++) wh[k] = Whh0[j * HID + k];
        const u64 pbias = splat2(bih0[j] + bhh0[j]);

        __syncthreads();

#pragma unroll 1
        for (int t = 0; t < TT; t++) {
            const float* xb = xbuf + (t & 1) * (IND * EE);

            u64 acc[8];
#pragma unroll
            for (int i = 0; i < 8; i++) acc[i] = pbias;

#pragma unroll
            for (int k = 0; k < IND; k++) {
                u64 pw = splat2(wi[k]);
                GACC(acc, xb + k * EE, pw);
            }
#pragma unroll
            for (int k = 0; k < HID; k++) {
                u64 pw = splat2(wh[k]);
                GACC(acc, hs + k * ES, pw);
            }

#pragma unroll
            for (int i = 0; i < 8; i++) {
                float2 v = unpack2(acc[i]);
                float a0 = (gt == 2) ? ftanh(v.x) : fsig(v.x);
                float a1 = (gt == 2) ? ftanh(v.y) : fsig(v.y);
                act[(2 * i) * AS + j]     = a0;
                act[(2 * i + 1) * AS + j] = a1;
            }
            __syncthreads();

            // distributed cell update: all 256 threads, 4 cells each
            float* h1t = h1seq + t * HID * ES;
#pragma unroll
            for (int q = 0; q < 4; q++) {
                int e = eb + q;
                const float* ae = act + e * AS;
                float ig = ae[unit];
                float fg = ae[64 + unit];
                float gg = ae[128 + unit];
                float og = ae[192 + unit];
                c[q] = fg * c[q] + ig * gg;
                float h = og * ftanh(c[q]);
                hs[unit * ES + e] = h;
                h1t[unit * ES + e] = h;
            }
            // stage x for t+1 (double buffer)
            if (t + 1 < TT) {
                float* xn = xbuf + ((t + 1) & 1) * (IND * EE);
                for (int idx = j; idx < IND * EE; idx += 256) {
                    int e = idx & (EE - 1), k = idx >> 4;
                    xn[k * EE + e] = x[(size_t)(e0 + e) * (TT * IND) + (t + 1) * IND + k];
                }
            }
            __syncthreads();
        }
    }

    // reset state for layer 1
#pragma unroll
    for (int q = 0; q < 4; q++) c[q] = 0.0f;
    for (int idx = j; idx < HID * ES; idx += 256) hs[idx] = 0.0f;

    // ================= Layer 1 =================
    {
        float wi[HID], wh[HID];
#pragma unroll
        for (int k = 0; k < HID; k++) wi[k] = Wih1[j * HID + k];
#pragma unroll
        for (int k = 0; k < HID; k++) wh[k] = Whh1[j * HID + k];
        const u64 pbias = splat2(bih1[j] + bhh1[j]);

        __syncthreads();

#pragma unroll 1
        for (int t = 0; t < TT; t++) {
            const float* h1t = h1seq + t * HID * ES;

            u64 acc[8];
#pragma unroll
            for (int i = 0; i < 8; i++) acc[i] = pbias;

#pragma unroll
            for (int k = 0; k < HID; k++) {
                u64 pa = splat2(wi[k]);
                u64 pb = splat2(wh[k]);
                GACC(acc, h1t + k * ES, pa);
                GACC(acc, hs + k * ES, pb);
            }

#pragma unroll
            for (int i = 0; i < 8; i++) {
                float2 v = unpack2(acc[i]);
                float a0 = (gt == 2) ? ftanh(v.x) : fsig(v.x);
                float a1 = (gt == 2) ? ftanh(v.y) : fsig(v.y);
                act[(2 * i) * AS + j]     = a0;
                act[(2 * i + 1) * AS + j] = a1;
            }
            __syncthreads();

#pragma unroll
            for (int q = 0; q < 4; q++) {
                int e = eb + q;
                const float* ae = act + e * AS;
                float ig = ae[unit];
                float fg = ae[64 + unit];
                float gg = ae[128 + unit];
                float og = ae[192 + unit];
                c[q] = fg * c[q] + ig * gg;
                float h = og * ftanh(c[q]);
                hs[unit * ES + e] = h;
            }
            __syncthreads();
        }
    }

    // ================= Linear head =================
    // hs holds h2[T-1] as [unit][e] (stride ES)
    if (j < OUTD * EE) {
        int e = j & (EE - 1);
        int o = j >> 4;
        float s = blin_s[o];
#pragma unroll
        for (int k = 0; k < HID; k++)
            s += wlin[o * HID + k] * hs[k * ES + e];
        out[(size_t)(e0 + e) * OUTD + o] = s;
    }
}

extern "C" void kernel_launch(void* const* d_in, const int* in_sizes, int n_in,
                              void* d_out, int out_size)
{
    const float* x    = (const float*)d_in[0];
    const float* Wih0 = (const float*)d_in[1];
    const float* Whh0 = (const float*)d_in[2];
    const float* bih0 = (const float*)d_in[3];
    const float* bhh0 = (const float*)d_in[4];
    const float* Wih1 = (const float*)d_in[5];
    const float* Whh1 = (const float*)d_in[6];
    const float* bih1 = (const float*)d_in[7];
    const float* bhh1 = (const float*)d_in[8];
    const float* Wlin = (const float*)d_in[9];
    const float* blin = (const float*)d_in[10];
    float* out = (float*)d_out;

    int B = in_sizes[0] / (TT * IND);   // 16384
    int grid = B / EE;                  // 1024

    cudaFuncSetAttribute(rnn_fused_kernel,
                         cudaFuncAttributeMaxDynamicSharedMemorySize, SMEM_BYTES);
    rnn_fused_kernel<<<grid, 256, SMEM_BYTES>>>(
        x, Wih0, Whh0, bih0, bhh0, Wih1, Whh1, bih1, bhh1, Wlin, blin, out);
}